// round 8
// baseline (speedup 1.0000x reference)
#include <cuda_runtime.h>
#include <cstdint>

#define S_LEN 512
#define BATCH 32
#define HID 256
#define NTAG 11
#define START_TAG 9
#define STOP_TAG 10
#define NEGV -1000.0f
#define NCTA_LSTM 128

// ---------------- static device scratch ----------------
__device__ float g_xe[S_LEN * BATCH * HID];                 // [s*32+b][256]
__device__ float g_gates[2 * S_LEN * BATCH * 4 * HID];      // [dir][s][b][1024] (reused L0/L1)
__device__ float g_h0[S_LEN * BATCH * 2 * HID];             // [s*32+b][512]
__device__ float g_h1[S_LEN * BATCH * 2 * HID];
__device__ float g_feats[S_LEN * BATCH * NTAG];             // [s*32+b][11]
__device__ unsigned g_cnt[16 * 32];                         // per-group barrier counters (128B apart)

// ---------------- packed f32x2 helpers ----------------
__device__ __forceinline__ void vfma(unsigned long long& acc,
                                     unsigned long long a, unsigned long long b) {
    asm("fma.rn.f32x2 %0, %1, %2, %0;" : "+l"(acc) : "l"(a), "l"(b));
}
__device__ __forceinline__ unsigned long long dup2(float x) {
    unsigned long long r;
    asm("mov.b64 %0, {%1,%1};" : "=l"(r) : "f"(x));
    return r;
}
__device__ __forceinline__ float2 unpk(unsigned long long v) {
    float2 r;
    asm("mov.b64 {%0,%1}, %2;" : "=f"(r.x), "=f"(r.y) : "l"(v));
    return r;
}
__device__ __forceinline__ float red2(unsigned long long v) {
    float2 r = unpk(v);
    return r.x + r.y;
}

// ---------------- embedding gather ----------------
__global__ __launch_bounds__(256)
void embed_kernel(const int* __restrict__ x,
                  const float* __restrict__ emb,
                  float* __restrict__ xe) {
    int idx = blockIdx.x * 256 + threadIdx.x;   // 16384 rows * 64 float4
    int pos = idx >> 6, h4 = idx & 63;
    int s = pos >> 5, b = pos & 31;
    int tok = x[b * S_LEN + s];
    ((float4*)xe)[((size_t)pos << 6) + h4] = ((const float4*)emb)[(size_t)tok * 64 + h4];
}

// ---------------- SGEMM: C[m][n] = sum_k A[m][k]*W[n][k] + bias[n] ----------------
// 128x64 tile, 256 threads, software-pipelined staging (LDG for kt+1 hidden
// under FMA of kt). f32x2 packed over row pairs.
// M = 16384 (grid.y*128), N = 1024 (grid.x*64), C row stride 1024.
__global__ __launch_bounds__(256)
void sgemm_bias(const float* __restrict__ A,
                const float* __restrict__ W,
                const float* __restrict__ bias,
                float* __restrict__ C,
                int K) {
    __shared__ __align__(16) float As[16][128];
    __shared__ __align__(16) float Bs[16][64];
    int tid = threadIdx.x;
    int m0 = blockIdx.y << 7;
    int n0 = blockIdx.x << 6;
    int tx = tid & 15, ty = tid >> 4;
    int am = tid >> 1, ah = (tid & 1) << 3;
    int bn = tid >> 2, bk = (tid & 3) << 2;

    // acc2[p][j]: rows (2p,2p+1) packed, col j
    unsigned long long acc2[4][4];
#pragma unroll
    for (int p = 0; p < 4; ++p)
#pragma unroll
        for (int j = 0; j < 4; ++j) acc2[p][j] = 0ull;

    const float* Ap = A + (size_t)(m0 + am) * K + ah;
    const float* Wp = W + (size_t)(n0 + bn) * K + bk;

    // prologue: load tile 0
    float4 av0 = *(const float4*)(Ap);
    float4 av1 = *(const float4*)(Ap + 4);
    float4 bv  = *(const float4*)(Wp);

    for (int kt = 0; kt < K; kt += 16) {
        __syncthreads();
        As[ah + 0][am] = av0.x; As[ah + 1][am] = av0.y;
        As[ah + 2][am] = av0.z; As[ah + 3][am] = av0.w;
        As[ah + 4][am] = av1.x; As[ah + 5][am] = av1.y;
        As[ah + 6][am] = av1.z; As[ah + 7][am] = av1.w;
        Bs[bk + 0][bn] = bv.x; Bs[bk + 1][bn] = bv.y;
        Bs[bk + 2][bn] = bv.z; Bs[bk + 3][bn] = bv.w;
        __syncthreads();

        // prefetch next tile (independent of smem) — hides LDG under FMA
        if (kt + 16 < K) {
            av0 = *(const float4*)(Ap + kt + 16);
            av1 = *(const float4*)(Ap + kt + 20);
            bv  = *(const float4*)(Wp + kt + 16);
        }

#pragma unroll
        for (int k = 0; k < 16; ++k) {
            ulonglong2 a01 = *(const ulonglong2*)&As[k][ty << 3];
            ulonglong2 a23 = *(const ulonglong2*)&As[k][(ty << 3) + 4];
            float4 bb = *(const float4*)&Bs[k][tx << 2];
            unsigned long long b0 = dup2(bb.x), b1 = dup2(bb.y);
            unsigned long long b2 = dup2(bb.z), b3 = dup2(bb.w);
            vfma(acc2[0][0], a01.x, b0); vfma(acc2[0][1], a01.x, b1);
            vfma(acc2[0][2], a01.x, b2); vfma(acc2[0][3], a01.x, b3);
            vfma(acc2[1][0], a01.y, b0); vfma(acc2[1][1], a01.y, b1);
            vfma(acc2[1][2], a01.y, b2); vfma(acc2[1][3], a01.y, b3);
            vfma(acc2[2][0], a23.x, b0); vfma(acc2[2][1], a23.x, b1);
            vfma(acc2[2][2], a23.x, b2); vfma(acc2[2][3], a23.x, b3);
            vfma(acc2[3][0], a23.y, b0); vfma(acc2[3][1], a23.y, b1);
            vfma(acc2[3][2], a23.y, b2); vfma(acc2[3][3], a23.y, b3);
        }
    }
    float4 bsv = *(const float4*)&bias[n0 + (tx << 2)];
#pragma unroll
    for (int p = 0; p < 4; ++p) {
        float2 c0 = unpk(acc2[p][0]);
        float2 c1 = unpk(acc2[p][1]);
        float2 c2 = unpk(acc2[p][2]);
        float2 c3 = unpk(acc2[p][3]);
        float4 oe, oo;
        oe.x = c0.x + bsv.x; oe.y = c1.x + bsv.y; oe.z = c2.x + bsv.z; oe.w = c3.x + bsv.w;
        oo.x = c0.y + bsv.x; oo.y = c1.y + bsv.y; oo.z = c2.y + bsv.z; oo.w = c3.y + bsv.w;
        *(float4*)&C[(size_t)(m0 + (ty << 3) + 2 * p) * 1024 + n0 + (tx << 2)] = oe;
        *(float4*)&C[(size_t)(m0 + (ty << 3) + 2 * p + 1) * 1024 + n0 + (tx << 2)] = oo;
    }
}

// ---------------- persistent BiLSTM layer (R5 version: gmem h exchange) ----------------
__device__ __forceinline__ float sigm(float x) { return 1.f / (1.f + __expf(-x)); }

// grid = 128 CTAs: dir(2) x hslice(8: 32 cols) x bslice(8: 4 batches), 256 thr.
// whh slice held entirely in registers (128 floats/thread).
// Sync: 16 independent groups of 8 CTAs (same dir, same bslice), monotonic counters.
__global__ __launch_bounds__(256, 1)
void lstm_layer(const float* __restrict__ gates,    // [2][S][B][1024] = Wx+b
                const float* __restrict__ whhF,     // [1024][256]
                const float* __restrict__ whhB,
                float* __restrict__ hout) {         // [S][B][512]
    __shared__ __align__(16) float hbuf[1024];      // [4 batches][256]
    __shared__ __align__(16) float psum[1024];      // [2q * 4 batches][128]

    const int tid = threadIdx.x;
    const int bx = blockIdx.x;
    const int dir = bx >> 6;
    const int hs = (bx >> 3) & 7;
    const int bs = bx & 7;
    const float* whh = dir ? whhB : whhF;

    const int jj = tid & 31;
    const int gg = (tid >> 5) & 3;
    const int q = tid >> 7;
    const int grp = dir * 8 + bs;

    // load whh row slice into registers: gate-row = gg*256 + hs*32 + jj, K-half q
    unsigned long long w2[64];
    {
        const float* wptr = whh + ((size_t)(gg << 8) + (hs << 5) + jj) * 256 + (q << 7);
#pragma unroll
        for (int i = 0; i < 32; ++i) {
            ulonglong2 v = *(const ulonglong2*)(wptr + (i << 2));
            w2[2 * i] = v.x; w2[2 * i + 1] = v.y;
        }
    }

    const int ob = tid >> 5;                // tid<128: owned batch-in-slice
    const int obg = (bs << 2) + ob;         // global batch
    float c = 0.f;

    for (int t = 0; t < S_LEN; ++t) {
        int s = dir ? (S_LEN - 1 - t) : t;

        // prefetch gates (no dependence on barrier) — hidden under FMA loop
        float gxi = 0.f, gxf = 0.f, gxg = 0.f, gxo = 0.f;
        if (tid < 128) {
            const float* gp = &gates[(size_t)(((dir * S_LEN + s) << 5) + obg) * 1024 + (hs << 5) + jj];
            gxi = gp[0]; gxf = gp[256]; gxg = gp[512]; gxo = gp[768];
        }

        // stage h_{t-1} for 4 batches (own direction half)
        if (t == 0) {
            *(float4*)&hbuf[tid << 2] = make_float4(0.f, 0.f, 0.f, 0.f);
        } else {
            int sp = dir ? (s + 1) : (s - 1);
            int bb = tid >> 6, k4 = tid & 63;
            *(float4*)&hbuf[bb * 256 + (k4 << 2)] =
                *(const float4*)&hout[(size_t)((sp << 5) + (bs << 2) + bb) * 512 + (dir << 8) + (k4 << 2)];
        }
        __syncthreads();

        unsigned long long a0 = 0ull, a1 = 0ull, a2 = 0ull, a3 = 0ull;
        const float* hb = hbuf + (q << 7);
#pragma unroll
        for (int i = 0; i < 32; ++i) {
            ulonglong2 x0 = *(const ulonglong2*)(hb + (i << 2));
            ulonglong2 x1 = *(const ulonglong2*)(hb + 256 + (i << 2));
            ulonglong2 x2 = *(const ulonglong2*)(hb + 512 + (i << 2));
            ulonglong2 x3 = *(const ulonglong2*)(hb + 768 + (i << 2));
            vfma(a0, w2[2 * i], x0.x); vfma(a0, w2[2 * i + 1], x0.y);
            vfma(a1, w2[2 * i], x1.x); vfma(a1, w2[2 * i + 1], x1.y);
            vfma(a2, w2[2 * i], x2.x); vfma(a2, w2[2 * i + 1], x2.y);
            vfma(a3, w2[2 * i], x3.x); vfma(a3, w2[2 * i + 1], x3.y);
        }
        int pb = (gg << 5) + jj;
        psum[((q << 2) + 0) * 128 + pb] = red2(a0);
        psum[((q << 2) + 1) * 128 + pb] = red2(a1);
        psum[((q << 2) + 2) * 128 + pb] = red2(a2);
        psum[((q << 2) + 3) * 128 + pb] = red2(a3);
        __syncthreads();

        if (tid < 128) {
            float ri = psum[ob * 128 + jj]      + psum[(4 + ob) * 128 + jj];
            float rf = psum[ob * 128 + 32 + jj] + psum[(4 + ob) * 128 + 32 + jj];
            float rg = psum[ob * 128 + 64 + jj] + psum[(4 + ob) * 128 + 64 + jj];
            float ro = psum[ob * 128 + 96 + jj] + psum[(4 + ob) * 128 + 96 + jj];
            float iv = sigm(gxi + ri);
            float fv = sigm(gxf + rf);
            float gv = tanhf(gxg + rg);
            float ov = sigm(gxo + ro);
            c = fv * c + iv * gv;
            float h = ov * tanhf(c);
            hout[(size_t)((s << 5) + obg) * 512 + (dir << 8) + (hs << 5) + jj] = h;
        }

        // group barrier: 8 CTAs sharing (dir, bs), monotonic counter
        __syncthreads();
        if (tid == 0) {
            __threadfence();
            atomicAdd(&g_cnt[grp << 5], 1u);
            unsigned tgt = 8u * (unsigned)(t + 1);
            while (*(volatile unsigned*)&g_cnt[grp << 5] < tgt) {}
            __threadfence();
        }
        __syncthreads();
    }
}

// ---------------- feats = h1 @ w_out^T + b_out ----------------
__global__ __launch_bounds__(256)
void feats_kernel(const float* __restrict__ h,
                  const float* __restrict__ w_out,
                  const float* __restrict__ b_out,
                  float* __restrict__ feats) {
    __shared__ float ws[NTAG * 512];
    int tid = threadIdx.x;
    for (int i = tid; i < NTAG * 512; i += 256) ws[i] = w_out[i];
    __syncthreads();
    int warp = tid >> 5, lane = tid & 31;
    int m = blockIdx.x * 8 + warp;          // 0..16383
    float hreg[16];
#pragma unroll
    for (int i = 0; i < 16; ++i) hreg[i] = h[(size_t)m * 512 + i * 32 + lane];
#pragma unroll
    for (int tg = 0; tg < NTAG; ++tg) {
        float acc = 0.f;
#pragma unroll
        for (int i = 0; i < 16; ++i) acc += hreg[i] * ws[tg * 512 + i * 32 + lane];
#pragma unroll
        for (int off = 16; off; off >>= 1) acc += __shfl_down_sync(0xffffffffu, acc, off);
        if (lane == 0) feats[(size_t)m * NTAG + tg] = acc + b_out[tg];
    }
}

// ---------------- Viterbi (1 warp per batch) ----------------
__global__ __launch_bounds__(32)
void viterbi_kernel(const float* __restrict__ feats,
                    const float* __restrict__ trans,
                    float* __restrict__ out) {
    __shared__ unsigned char bps[S_LEN][16];
    int b = blockIdx.x, t = threadIdx.x;
    int tc = (t < NTAG) ? t : NTAG - 1;
    float tr[NTAG];
#pragma unroll
    for (int p = 0; p < NTAG; ++p) tr[p] = trans[tc * NTAG + p];
    float fv = (t == START_TAG) ? 0.f : NEGV;

    for (int s = 0; s < S_LEN; ++s) {
        float best = -3.4e38f; int bp = 0;
#pragma unroll
        for (int p = 0; p < NTAG; ++p) {
            float fp = __shfl_sync(0xffffffffu, fv, p);
            float v = fp + tr[p];
            if (v > best) { best = v; bp = p; }
        }
        float feat = (t < NTAG) ? feats[(size_t)((s << 5) + b) * NTAG + t] : 0.f;
        fv = best + feat;
        if (t < NTAG) bps[s][t] = (unsigned char)bp;
    }

    float term = (t < NTAG) ? fv + trans[STOP_TAG * NTAG + t] : -3.4e38f;
    int idx = t;
#pragma unroll
    for (int off = 16; off; off >>= 1) {
        float ov = __shfl_down_sync(0xffffffffu, term, off);
        int oi = __shfl_down_sync(0xffffffffu, idx, off);
        if (ov > term || (ov == term && oi < idx)) { term = ov; idx = oi; }
    }
    if (t == 0) {
        out[b] = term;
        int tag = idx;
        for (int s = S_LEN - 1; s >= 0; --s) {
            out[32 + b * S_LEN + s] = (float)tag;
            tag = bps[s][tag];
        }
    }
}

// ---------------- launcher ----------------
extern "C" void kernel_launch(void* const* d_in, const int* in_sizes, int n_in,
                              void* d_out, int out_size) {
    const int*   x      = (const int*)d_in[0];
    const float* emb    = (const float*)d_in[2];
    const float* wih0f  = (const float*)d_in[3];
    const float* whh0f  = (const float*)d_in[4];
    const float* b0f    = (const float*)d_in[5];
    const float* wih0b  = (const float*)d_in[6];
    const float* whh0b  = (const float*)d_in[7];
    const float* b0b    = (const float*)d_in[8];
    const float* wih1f  = (const float*)d_in[9];
    const float* whh1f  = (const float*)d_in[10];
    const float* b1f    = (const float*)d_in[11];
    const float* wih1b  = (const float*)d_in[12];
    const float* whh1b  = (const float*)d_in[13];
    const float* b1b    = (const float*)d_in[14];
    const float* w_out  = (const float*)d_in[15];
    const float* b_out  = (const float*)d_in[16];
    const float* trans  = (const float*)d_in[17];
    float* out = (float*)d_out;

    float* xe = nullptr; float* gates = nullptr; float* h0 = nullptr;
    float* h1 = nullptr; float* feats = nullptr; unsigned* cnt = nullptr;
    cudaGetSymbolAddress((void**)&xe, g_xe);
    cudaGetSymbolAddress((void**)&gates, g_gates);
    cudaGetSymbolAddress((void**)&h0, g_h0);
    cudaGetSymbolAddress((void**)&h1, g_h1);
    cudaGetSymbolAddress((void**)&feats, g_feats);
    cudaGetSymbolAddress((void**)&cnt, g_cnt);

    const size_t dirStride = (size_t)S_LEN * BATCH * 1024;

    embed_kernel<<<4096, 256>>>(x, emb, xe);

    sgemm_bias<<<dim3(16, 128), 256>>>(xe, wih0f, b0f, gates, HID);
    sgemm_bias<<<dim3(16, 128), 256>>>(xe, wih0b, b0b, gates + dirStride, HID);
    cudaMemsetAsync(cnt, 0, 16 * 32 * sizeof(unsigned));
    lstm_layer<<<NCTA_LSTM, 256>>>(gates, whh0f, whh0b, h0);

    sgemm_bias<<<dim3(16, 128), 256>>>(h0, wih1f, b1f, gates, 2 * HID);
    sgemm_bias<<<dim3(16, 128), 256>>>(h0, wih1b, b1b, gates + dirStride, 2 * HID);
    cudaMemsetAsync(cnt, 0, 16 * 32 * sizeof(unsigned));
    lstm_layer<<<NCTA_LSTM, 256>>>(gates, whh1f, whh1b, h1);

    feats_kernel<<<2048, 256>>>(h1, w_out, b_out, feats);
    viterbi_kernel<<<BATCH, 32>>>(feats, trans, out);
}

// round 9
// speedup vs baseline: 1.4685x; 1.4685x over previous
#include <cuda_runtime.h>
#include <cstdint>

#define S_LEN 512
#define BATCH 32
#define HID 256
#define NTAG 11
#define START_TAG 9
#define STOP_TAG 10
#define NEGV -1000.0f
#define NCTA_LSTM 128

// ---------------- static device scratch ----------------
__device__ float g_xe[S_LEN * BATCH * HID];                 // [s*32+b][256]
__device__ float g_gates[2 * S_LEN * BATCH * 4 * HID];      // [dir][s][b][1024] (reused L0/L1)
__device__ float g_h0[S_LEN * BATCH * 2 * HID];             // [s*32+b][512]
__device__ float g_h1[S_LEN * BATCH * 2 * HID];
__device__ float g_feats[S_LEN * BATCH * NTAG];             // [s*32+b][11]
__device__ unsigned g_cnt[16 * 32];                         // per-group barrier counters (128B apart)

// ---------------- packed f32x2 helpers ----------------
__device__ __forceinline__ void vfma(unsigned long long& acc,
                                     unsigned long long a, unsigned long long b) {
    asm("fma.rn.f32x2 %0, %1, %2, %0;" : "+l"(acc) : "l"(a), "l"(b));
}
__device__ __forceinline__ unsigned long long dup2(float x) {
    unsigned long long r;
    asm("mov.b64 %0, {%1,%1};" : "=l"(r) : "f"(x));
    return r;
}
__device__ __forceinline__ float2 unpk(unsigned long long v) {
    float2 r;
    asm("mov.b64 {%0,%1}, %2;" : "=f"(r.x), "=f"(r.y) : "l"(v));
    return r;
}
__device__ __forceinline__ float red2(unsigned long long v) {
    float2 r = unpk(v);
    return r.x + r.y;
}

// ---------------- embedding gather ----------------
__global__ __launch_bounds__(256)
void embed_kernel(const int* __restrict__ x,
                  const float* __restrict__ emb,
                  float* __restrict__ xe) {
    int idx = blockIdx.x * 256 + threadIdx.x;   // 16384 rows * 64 float4
    int pos = idx >> 6, h4 = idx & 63;
    int s = pos >> 5, b = pos & 31;
    int tok = x[b * S_LEN + s];
    ((float4*)xe)[((size_t)pos << 6) + h4] = ((const float4*)emb)[(size_t)tok * 64 + h4];
}

// ---------------- SGEMM: C[m][n] = sum_k A[m][k]*W[n][k] + bias[n] ----------------
// 128x64 tile, 256 threads, double-buffered smem: one __syncthreads per k-tile,
// LDG of tile kt+1 issued before FMA of tile kt. f32x2 packed over row pairs.
// M = 16384 (grid.y*128), N = 1024 (grid.x*64), C row stride 1024.
__global__ __launch_bounds__(256)
void sgemm_bias(const float* __restrict__ A,
                const float* __restrict__ W,
                const float* __restrict__ bias,
                float* __restrict__ C,
                int K) {
    __shared__ __align__(16) float As[2][16][128];
    __shared__ __align__(16) float Bs[2][16][64];
    int tid = threadIdx.x;
    int m0 = blockIdx.y << 7;
    int n0 = blockIdx.x << 6;
    int tx = tid & 15, ty = tid >> 4;
    int am = tid >> 1, ah = (tid & 1) << 3;
    int bn = tid >> 2, bk = (tid & 3) << 2;

    // acc2[p][j]: rows (2p,2p+1) packed, col j
    unsigned long long acc2[4][4];
#pragma unroll
    for (int p = 0; p < 4; ++p)
#pragma unroll
        for (int j = 0; j < 4; ++j) acc2[p][j] = 0ull;

    const float* Ap = A + (size_t)(m0 + am) * K + ah;
    const float* Wp = W + (size_t)(n0 + bn) * K + bk;

    // prologue: load + store tile 0 into buffer 0
    {
        float4 av0 = *(const float4*)(Ap);
        float4 av1 = *(const float4*)(Ap + 4);
        float4 bv  = *(const float4*)(Wp);
        As[0][ah + 0][am] = av0.x; As[0][ah + 1][am] = av0.y;
        As[0][ah + 2][am] = av0.z; As[0][ah + 3][am] = av0.w;
        As[0][ah + 4][am] = av1.x; As[0][ah + 5][am] = av1.y;
        As[0][ah + 6][am] = av1.z; As[0][ah + 7][am] = av1.w;
        Bs[0][bk + 0][bn] = bv.x; Bs[0][bk + 1][bn] = bv.y;
        Bs[0][bk + 2][bn] = bv.z; Bs[0][bk + 3][bn] = bv.w;
    }
    __syncthreads();

    const int nt = K >> 4;
    for (int kt = 0; kt < nt; ++kt) {
        const int cur = kt & 1, nxb = cur ^ 1;
        const bool more = (kt + 1) < nt;

        // LDG tile kt+1 early — hidden under the FMA loop below
        float4 av0, av1, bv;
        if (more) {
            av0 = *(const float4*)(Ap + (kt + 1) * 16);
            av1 = *(const float4*)(Ap + (kt + 1) * 16 + 4);
            bv  = *(const float4*)(Wp + (kt + 1) * 16);
        }

#pragma unroll
        for (int k = 0; k < 16; ++k) {
            ulonglong2 a01 = *(const ulonglong2*)&As[cur][k][ty << 3];
            ulonglong2 a23 = *(const ulonglong2*)&As[cur][k][(ty << 3) + 4];
            float4 bb = *(const float4*)&Bs[cur][k][tx << 2];
            unsigned long long b0 = dup2(bb.x), b1 = dup2(bb.y);
            unsigned long long b2 = dup2(bb.z), b3 = dup2(bb.w);
            vfma(acc2[0][0], a01.x, b0); vfma(acc2[0][1], a01.x, b1);
            vfma(acc2[0][2], a01.x, b2); vfma(acc2[0][3], a01.x, b3);
            vfma(acc2[1][0], a01.y, b0); vfma(acc2[1][1], a01.y, b1);
            vfma(acc2[1][2], a01.y, b2); vfma(acc2[1][3], a01.y, b3);
            vfma(acc2[2][0], a23.x, b0); vfma(acc2[2][1], a23.x, b1);
            vfma(acc2[2][2], a23.x, b2); vfma(acc2[2][3], a23.x, b3);
            vfma(acc2[3][0], a23.y, b0); vfma(acc2[3][1], a23.y, b1);
            vfma(acc2[3][2], a23.y, b2); vfma(acc2[3][3], a23.y, b3);
        }

        // STS tile kt+1 into the other buffer; its previous readers (iteration
        // kt-1) are protected by the barrier at the end of that iteration.
        if (more) {
            As[nxb][ah + 0][am] = av0.x; As[nxb][ah + 1][am] = av0.y;
            As[nxb][ah + 2][am] = av0.z; As[nxb][ah + 3][am] = av0.w;
            As[nxb][ah + 4][am] = av1.x; As[nxb][ah + 5][am] = av1.y;
            As[nxb][ah + 6][am] = av1.z; As[nxb][ah + 7][am] = av1.w;
            Bs[nxb][bk + 0][bn] = bv.x; Bs[nxb][bk + 1][bn] = bv.y;
            Bs[nxb][bk + 2][bn] = bv.z; Bs[nxb][bk + 3][bn] = bv.w;
        }
        __syncthreads();
    }

    float4 bsv = *(const float4*)&bias[n0 + (tx << 2)];
#pragma unroll
    for (int p = 0; p < 4; ++p) {
        float2 c0 = unpk(acc2[p][0]);
        float2 c1 = unpk(acc2[p][1]);
        float2 c2 = unpk(acc2[p][2]);
        float2 c3 = unpk(acc2[p][3]);
        float4 oe, oo;
        oe.x = c0.x + bsv.x; oe.y = c1.x + bsv.y; oe.z = c2.x + bsv.z; oe.w = c3.x + bsv.w;
        oo.x = c0.y + bsv.x; oo.y = c1.y + bsv.y; oo.z = c2.y + bsv.z; oo.w = c3.y + bsv.w;
        *(float4*)&C[(size_t)(m0 + (ty << 3) + 2 * p) * 1024 + n0 + (tx << 2)] = oe;
        *(float4*)&C[(size_t)(m0 + (ty << 3) + 2 * p + 1) * 1024 + n0 + (tx << 2)] = oo;
    }
}

// ---------------- persistent BiLSTM layer (R5 version: gmem h exchange) ----------------
__device__ __forceinline__ float sigm(float x) { return 1.f / (1.f + __expf(-x)); }

// grid = 128 CTAs: dir(2) x hslice(8: 32 cols) x bslice(8: 4 batches), 256 thr.
// whh slice held entirely in registers (128 floats/thread).
// Sync: 16 independent groups of 8 CTAs (same dir, same bslice), monotonic counters.
__global__ __launch_bounds__(256, 1)
void lstm_layer(const float* __restrict__ gates,    // [2][S][B][1024] = Wx+b
                const float* __restrict__ whhF,     // [1024][256]
                const float* __restrict__ whhB,
                float* __restrict__ hout) {         // [S][B][512]
    __shared__ __align__(16) float hbuf[1024];      // [4 batches][256]
    __shared__ __align__(16) float psum[1024];      // [2q * 4 batches][128]

    const int tid = threadIdx.x;
    const int bx = blockIdx.x;
    const int dir = bx >> 6;
    const int hs = (bx >> 3) & 7;
    const int bs = bx & 7;
    const float* whh = dir ? whhB : whhF;

    const int jj = tid & 31;
    const int gg = (tid >> 5) & 3;
    const int q = tid >> 7;
    const int grp = dir * 8 + bs;

    // load whh row slice into registers: gate-row = gg*256 + hs*32 + jj, K-half q
    unsigned long long w2[64];
    {
        const float* wptr = whh + ((size_t)(gg << 8) + (hs << 5) + jj) * 256 + (q << 7);
#pragma unroll
        for (int i = 0; i < 32; ++i) {
            ulonglong2 v = *(const ulonglong2*)(wptr + (i << 2));
            w2[2 * i] = v.x; w2[2 * i + 1] = v.y;
        }
    }

    const int ob = tid >> 5;                // tid<128: owned batch-in-slice
    const int obg = (bs << 2) + ob;         // global batch
    float c = 0.f;

    for (int t = 0; t < S_LEN; ++t) {
        int s = dir ? (S_LEN - 1 - t) : t;

        // prefetch gates (no dependence on barrier) — hidden under FMA loop
        float gxi = 0.f, gxf = 0.f, gxg = 0.f, gxo = 0.f;
        if (tid < 128) {
            const float* gp = &gates[(size_t)(((dir * S_LEN + s) << 5) + obg) * 1024 + (hs << 5) + jj];
            gxi = gp[0]; gxf = gp[256]; gxg = gp[512]; gxo = gp[768];
        }

        // stage h_{t-1} for 4 batches (own direction half)
        if (t == 0) {
            *(float4*)&hbuf[tid << 2] = make_float4(0.f, 0.f, 0.f, 0.f);
        } else {
            int sp = dir ? (s + 1) : (s - 1);
            int bb = tid >> 6, k4 = tid & 63;
            *(float4*)&hbuf[bb * 256 + (k4 << 2)] =
                *(const float4*)&hout[(size_t)((sp << 5) + (bs << 2) + bb) * 512 + (dir << 8) + (k4 << 2)];
        }
        __syncthreads();

        unsigned long long a0 = 0ull, a1 = 0ull, a2 = 0ull, a3 = 0ull;
        const float* hb = hbuf + (q << 7);
#pragma unroll
        for (int i = 0; i < 32; ++i) {
            ulonglong2 x0 = *(const ulonglong2*)(hb + (i << 2));
            ulonglong2 x1 = *(const ulonglong2*)(hb + 256 + (i << 2));
            ulonglong2 x2 = *(const ulonglong2*)(hb + 512 + (i << 2));
            ulonglong2 x3 = *(const ulonglong2*)(hb + 768 + (i << 2));
            vfma(a0, w2[2 * i], x0.x); vfma(a0, w2[2 * i + 1], x0.y);
            vfma(a1, w2[2 * i], x1.x); vfma(a1, w2[2 * i + 1], x1.y);
            vfma(a2, w2[2 * i], x2.x); vfma(a2, w2[2 * i + 1], x2.y);
            vfma(a3, w2[2 * i], x3.x); vfma(a3, w2[2 * i + 1], x3.y);
        }
        int pb = (gg << 5) + jj;
        psum[((q << 2) + 0) * 128 + pb] = red2(a0);
        psum[((q << 2) + 1) * 128 + pb] = red2(a1);
        psum[((q << 2) + 2) * 128 + pb] = red2(a2);
        psum[((q << 2) + 3) * 128 + pb] = red2(a3);
        __syncthreads();

        if (tid < 128) {
            float ri = psum[ob * 128 + jj]      + psum[(4 + ob) * 128 + jj];
            float rf = psum[ob * 128 + 32 + jj] + psum[(4 + ob) * 128 + 32 + jj];
            float rg = psum[ob * 128 + 64 + jj] + psum[(4 + ob) * 128 + 64 + jj];
            float ro = psum[ob * 128 + 96 + jj] + psum[(4 + ob) * 128 + 96 + jj];
            float iv = sigm(gxi + ri);
            float fv = sigm(gxf + rf);
            float gv = tanhf(gxg + rg);
            float ov = sigm(gxo + ro);
            c = fv * c + iv * gv;
            float h = ov * tanhf(c);
            hout[(size_t)((s << 5) + obg) * 512 + (dir << 8) + (hs << 5) + jj] = h;
        }

        // group barrier: 8 CTAs sharing (dir, bs), monotonic counter
        __syncthreads();
        if (tid == 0) {
            __threadfence();
            atomicAdd(&g_cnt[grp << 5], 1u);
            unsigned tgt = 8u * (unsigned)(t + 1);
            while (*(volatile unsigned*)&g_cnt[grp << 5] < tgt) {}
            __threadfence();
        }
        __syncthreads();
    }
}

// ---------------- feats = h1 @ w_out^T + b_out ----------------
__global__ __launch_bounds__(256)
void feats_kernel(const float* __restrict__ h,
                  const float* __restrict__ w_out,
                  const float* __restrict__ b_out,
                  float* __restrict__ feats) {
    __shared__ float ws[NTAG * 512];
    int tid = threadIdx.x;
    for (int i = tid; i < NTAG * 512; i += 256) ws[i] = w_out[i];
    __syncthreads();
    int warp = tid >> 5, lane = tid & 31;
    int m = blockIdx.x * 8 + warp;          // 0..16383
    float hreg[16];
#pragma unroll
    for (int i = 0; i < 16; ++i) hreg[i] = h[(size_t)m * 512 + i * 32 + lane];
#pragma unroll
    for (int tg = 0; tg < NTAG; ++tg) {
        float acc = 0.f;
#pragma unroll
        for (int i = 0; i < 16; ++i) acc += hreg[i] * ws[tg * 512 + i * 32 + lane];
#pragma unroll
        for (int off = 16; off; off >>= 1) acc += __shfl_down_sync(0xffffffffu, acc, off);
        if (lane == 0) feats[(size_t)m * NTAG + tg] = acc + b_out[tg];
    }
}

// ---------------- Viterbi (1 warp per batch) ----------------
__global__ __launch_bounds__(32)
void viterbi_kernel(const float* __restrict__ feats,
                    const float* __restrict__ trans,
                    float* __restrict__ out) {
    __shared__ unsigned char bps[S_LEN][16];
    int b = blockIdx.x, t = threadIdx.x;
    int tc = (t < NTAG) ? t : NTAG - 1;
    float tr[NTAG];
#pragma unroll
    for (int p = 0; p < NTAG; ++p) tr[p] = trans[tc * NTAG + p];
    float fv = (t == START_TAG) ? 0.f : NEGV;

    for (int s = 0; s < S_LEN; ++s) {
        float best = -3.4e38f; int bp = 0;
#pragma unroll
        for (int p = 0; p < NTAG; ++p) {
            float fp = __shfl_sync(0xffffffffu, fv, p);
            float v = fp + tr[p];
            if (v > best) { best = v; bp = p; }
        }
        float feat = (t < NTAG) ? feats[(size_t)((s << 5) + b) * NTAG + t] : 0.f;
        fv = best + feat;
        if (t < NTAG) bps[s][t] = (unsigned char)bp;
    }

    float term = (t < NTAG) ? fv + trans[STOP_TAG * NTAG + t] : -3.4e38f;
    int idx = t;
#pragma unroll
    for (int off = 16; off; off >>= 1) {
        float ov = __shfl_down_sync(0xffffffffu, term, off);
        int oi = __shfl_down_sync(0xffffffffu, idx, off);
        if (ov > term || (ov == term && oi < idx)) { term = ov; idx = oi; }
    }
    if (t == 0) {
        out[b] = term;
        int tag = idx;
        for (int s = S_LEN - 1; s >= 0; --s) {
            out[32 + b * S_LEN + s] = (float)tag;
            tag = bps[s][tag];
        }
    }
}

// ---------------- launcher ----------------
extern "C" void kernel_launch(void* const* d_in, const int* in_sizes, int n_in,
                              void* d_out, int out_size) {
    const int*   x      = (const int*)d_in[0];
    const float* emb    = (const float*)d_in[2];
    const float* wih0f  = (const float*)d_in[3];
    const float* whh0f  = (const float*)d_in[4];
    const float* b0f    = (const float*)d_in[5];
    const float* wih0b  = (const float*)d_in[6];
    const float* whh0b  = (const float*)d_in[7];
    const float* b0b    = (const float*)d_in[8];
    const float* wih1f  = (const float*)d_in[9];
    const float* whh1f  = (const float*)d_in[10];
    const float* b1f    = (const float*)d_in[11];
    const float* wih1b  = (const float*)d_in[12];
    const float* whh1b  = (const float*)d_in[13];
    const float* b1b    = (const float*)d_in[14];
    const float* w_out  = (const float*)d_in[15];
    const float* b_out  = (const float*)d_in[16];
    const float* trans  = (const float*)d_in[17];
    float* out = (float*)d_out;

    float* xe = nullptr; float* gates = nullptr; float* h0 = nullptr;
    float* h1 = nullptr; float* feats = nullptr; unsigned* cnt = nullptr;
    cudaGetSymbolAddress((void**)&xe, g_xe);
    cudaGetSymbolAddress((void**)&gates, g_gates);
    cudaGetSymbolAddress((void**)&h0, g_h0);
    cudaGetSymbolAddress((void**)&h1, g_h1);
    cudaGetSymbolAddress((void**)&feats, g_feats);
    cudaGetSymbolAddress((void**)&cnt, g_cnt);

    const size_t dirStride = (size_t)S_LEN * BATCH * 1024;

    embed_kernel<<<4096, 256>>>(x, emb, xe);

    sgemm_bias<<<dim3(16, 128), 256>>>(xe, wih0f, b0f, gates, HID);
    sgemm_bias<<<dim3(16, 128), 256>>>(xe, wih0b, b0b, gates + dirStride, HID);
    cudaMemsetAsync(cnt, 0, 16 * 32 * sizeof(unsigned));
    lstm_layer<<<NCTA_LSTM, 256>>>(gates, whh0f, whh0b, h0);

    sgemm_bias<<<dim3(16, 128), 256>>>(h0, wih1f, b1f, gates, 2 * HID);
    sgemm_bias<<<dim3(16, 128), 256>>>(h0, wih1b, b1b, gates + dirStride, 2 * HID);
    cudaMemsetAsync(cnt, 0, 16 * 32 * sizeof(unsigned));
    lstm_layer<<<NCTA_LSTM, 256>>>(gates, whh1f, whh1b, h1);

    feats_kernel<<<2048, 256>>>(h1, w_out, b_out, feats);
    viterbi_kernel<<<BATCH, 32>>>(feats, trans, out);
}

// round 11
// speedup vs baseline: 1.5876x; 1.0812x over previous
#include <cuda_runtime.h>
#include <cstdint>

#define S_LEN 512
#define BATCH 32
#define HID 256
#define NTAG 11
#define START_TAG 9
#define STOP_TAG 10
#define NEGV -1000.0f
#define NCTA_LSTM 128

// ---------------- static device scratch ----------------
__device__ float g_xe[S_LEN * BATCH * HID];                 // [s*32+b][256]
__device__ float g_gates[2 * S_LEN * BATCH * 4 * HID];      // [dir][s][b][1024] (reused L0/L1)
__device__ float g_h0[S_LEN * BATCH * 2 * HID];             // [s*32+b][512]
__device__ float g_h1[S_LEN * BATCH * 2 * HID];
__device__ float g_feats[S_LEN * BATCH * NTAG];             // [s*32+b][11]
__device__ unsigned g_flag[16 * 8 * 32];                    // [grp][hs] flags, 128B apart

// ---------------- packed f32x2 helpers ----------------
__device__ __forceinline__ void vfma(unsigned long long& acc,
                                     unsigned long long a, unsigned long long b) {
    asm("fma.rn.f32x2 %0, %1, %2, %0;" : "+l"(acc) : "l"(a), "l"(b));
}
__device__ __forceinline__ unsigned long long dup2(float x) {
    unsigned long long r;
    asm("mov.b64 %0, {%1,%1};" : "=l"(r) : "f"(x));
    return r;
}
__device__ __forceinline__ float2 unpk(unsigned long long v) {
    float2 r;
    asm("mov.b64 {%0,%1}, %2;" : "=f"(r.x), "=f"(r.y) : "l"(v));
    return r;
}
__device__ __forceinline__ float red2(unsigned long long v) {
    float2 r = unpk(v);
    return r.x + r.y;
}

// ---------------- embedding gather ----------------
__global__ __launch_bounds__(256)
void embed_kernel(const int* __restrict__ x,
                  const float* __restrict__ emb,
                  float* __restrict__ xe) {
    int idx = blockIdx.x * 256 + threadIdx.x;   // 16384 rows * 64 float4
    int pos = idx >> 6, h4 = idx & 63;
    int s = pos >> 5, b = pos & 31;
    int tok = x[b * S_LEN + s];
    ((float4*)xe)[((size_t)pos << 6) + h4] = ((const float4*)emb)[(size_t)tok * 64 + h4];
}

// ---------------- SGEMM: C[m][n] = sum_k A[m][k]*W[n][k] + bias[n] ----------------
// R5 version (best measured): 128x64 tile, 256 threads, f32x2 packed over row pairs.
// M = 16384 (grid.y*128), N = 1024 (grid.x*64), C row stride 1024.
__global__ __launch_bounds__(256)
void sgemm_bias(const float* __restrict__ A,
                const float* __restrict__ W,
                const float* __restrict__ bias,
                float* __restrict__ C,
                int K) {
    __shared__ __align__(16) float As[16][128];
    __shared__ __align__(16) float Bs[16][64];
    int tid = threadIdx.x;
    int m0 = blockIdx.y << 7;
    int n0 = blockIdx.x << 6;
    int tx = tid & 15, ty = tid >> 4;
    int am = tid >> 1, ah = (tid & 1) << 3;
    int bn = tid >> 2, bk = (tid & 3) << 2;

    // acc2[p][j]: rows (2p,2p+1) packed, col j
    unsigned long long acc2[4][4];
#pragma unroll
    for (int p = 0; p < 4; ++p)
#pragma unroll
        for (int j = 0; j < 4; ++j) acc2[p][j] = 0ull;

    const float* Ap = A + (size_t)(m0 + am) * K + ah;
    const float* Wp = W + (size_t)(n0 + bn) * K + bk;

    for (int kt = 0; kt < K; kt += 16) {
        float4 av0 = *(const float4*)(Ap + kt);
        float4 av1 = *(const float4*)(Ap + kt + 4);
        float4 bv  = *(const float4*)(Wp + kt);
        __syncthreads();
        As[ah + 0][am] = av0.x; As[ah + 1][am] = av0.y;
        As[ah + 2][am] = av0.z; As[ah + 3][am] = av0.w;
        As[ah + 4][am] = av1.x; As[ah + 5][am] = av1.y;
        As[ah + 6][am] = av1.z; As[ah + 7][am] = av1.w;
        Bs[bk + 0][bn] = bv.x; Bs[bk + 1][bn] = bv.y;
        Bs[bk + 2][bn] = bv.z; Bs[bk + 3][bn] = bv.w;
        __syncthreads();
#pragma unroll
        for (int k = 0; k < 16; ++k) {
            ulonglong2 a01 = *(const ulonglong2*)&As[k][ty << 3];
            ulonglong2 a23 = *(const ulonglong2*)&As[k][(ty << 3) + 4];
            float4 bb = *(const float4*)&Bs[k][tx << 2];
            unsigned long long b0 = dup2(bb.x), b1 = dup2(bb.y);
            unsigned long long b2 = dup2(bb.z), b3 = dup2(bb.w);
            vfma(acc2[0][0], a01.x, b0); vfma(acc2[0][1], a01.x, b1);
            vfma(acc2[0][2], a01.x, b2); vfma(acc2[0][3], a01.x, b3);
            vfma(acc2[1][0], a01.y, b0); vfma(acc2[1][1], a01.y, b1);
            vfma(acc2[1][2], a01.y, b2); vfma(acc2[1][3], a01.y, b3);
            vfma(acc2[2][0], a23.x, b0); vfma(acc2[2][1], a23.x, b1);
            vfma(acc2[2][2], a23.x, b2); vfma(acc2[2][3], a23.x, b3);
            vfma(acc2[3][0], a23.y, b0); vfma(acc2[3][1], a23.y, b1);
            vfma(acc2[3][2], a23.y, b2); vfma(acc2[3][3], a23.y, b3);
        }
    }
    float4 bsv = *(const float4*)&bias[n0 + (tx << 2)];
#pragma unroll
    for (int p = 0; p < 4; ++p) {
        float2 c0 = unpk(acc2[p][0]);
        float2 c1 = unpk(acc2[p][1]);
        float2 c2 = unpk(acc2[p][2]);
        float2 c3 = unpk(acc2[p][3]);
        float4 oe, oo;
        oe.x = c0.x + bsv.x; oe.y = c1.x + bsv.y; oe.z = c2.x + bsv.z; oe.w = c3.x + bsv.w;
        oo.x = c0.y + bsv.x; oo.y = c1.y + bsv.y; oo.z = c2.y + bsv.z; oo.w = c3.y + bsv.w;
        *(float4*)&C[(size_t)(m0 + (ty << 3) + 2 * p) * 1024 + n0 + (tx << 2)] = oe;
        *(float4*)&C[(size_t)(m0 + (ty << 3) + 2 * p + 1) * 1024 + n0 + (tx << 2)] = oo;
    }
}

// ---------------- persistent BiLSTM layer ----------------
__device__ __forceinline__ float sigm(float x) { return 1.f / (1.f + __expf(-x)); }

// grid = 128 CTAs: dir(2) x hslice(8: 32 cols) x bslice(8: 4 batches), 256 thr.
// whh slice held entirely in registers (128 floats/thread).
// Sync: 16 independent groups of 8 CTAs; distributed per-CTA flags, parallel poll.
__global__ __launch_bounds__(256, 1)
void lstm_layer(const float* __restrict__ gates,    // [2][S][B][1024] = Wx+b
                const float* __restrict__ whhF,     // [1024][256]
                const float* __restrict__ whhB,
                float* __restrict__ hout) {         // [S][B][512]
    __shared__ __align__(16) float hbuf[1024];      // [4 batches][256]
    __shared__ __align__(16) float psum[1024];      // [2q * 4 batches][128]

    const int tid = threadIdx.x;
    const int bx = blockIdx.x;
    const int dir = bx >> 6;
    const int hs = (bx >> 3) & 7;
    const int bs = bx & 7;
    const float* whh = dir ? whhB : whhF;

    const int jj = tid & 31;
    const int gg = (tid >> 5) & 3;
    const int q = tid >> 7;
    const int grp = dir * 8 + bs;

    // load whh row slice into registers: gate-row = gg*256 + hs*32 + jj, K-half q
    unsigned long long w2[64];
    {
        const float* wptr = whh + ((size_t)(gg << 8) + (hs << 5) + jj) * 256 + (q << 7);
#pragma unroll
        for (int i = 0; i < 32; ++i) {
            ulonglong2 v = *(const ulonglong2*)(wptr + (i << 2));
            w2[2 * i] = v.x; w2[2 * i + 1] = v.y;
        }
    }

    const int ob = tid >> 5;                // tid<128: owned batch-in-slice
    const int obg = (bs << 2) + ob;         // global batch
    float c = 0.f;

    unsigned* myflag = &g_flag[(grp << 8) + (hs << 5)];
    unsigned* peerflag = &g_flag[(grp << 8) + ((tid & 7) << 5)];

    for (int t = 0; t < S_LEN; ++t) {
        int s = dir ? (S_LEN - 1 - t) : t;

        // prefetch gates (no dependence on barrier) — hidden under FMA loop
        float gxi = 0.f, gxf = 0.f, gxg = 0.f, gxo = 0.f;
        if (tid < 128) {
            const float* gp = &gates[(size_t)(((dir * S_LEN + s) << 5) + obg) * 1024 + (hs << 5) + jj];
            gxi = gp[0]; gxf = gp[256]; gxg = gp[512]; gxo = gp[768];
        }

        // stage h_{t-1} for 4 batches (own direction half)
        if (t == 0) {
            *(float4*)&hbuf[tid << 2] = make_float4(0.f, 0.f, 0.f, 0.f);
        } else {
            int sp = dir ? (s + 1) : (s - 1);
            int bb = tid >> 6, k4 = tid & 63;
            *(float4*)&hbuf[bb * 256 + (k4 << 2)] =
                *(const float4*)&hout[(size_t)((sp << 5) + (bs << 2) + bb) * 512 + (dir << 8) + (k4 << 2)];
        }
        __syncthreads();

        unsigned long long a0 = 0ull, a1 = 0ull, a2 = 0ull, a3 = 0ull;
        const float* hb = hbuf + (q << 7);
#pragma unroll
        for (int i = 0; i < 32; ++i) {
            ulonglong2 x0 = *(const ulonglong2*)(hb + (i << 2));
            ulonglong2 x1 = *(const ulonglong2*)(hb + 256 + (i << 2));
            ulonglong2 x2 = *(const ulonglong2*)(hb + 512 + (i << 2));
            ulonglong2 x3 = *(const ulonglong2*)(hb + 768 + (i << 2));
            vfma(a0, w2[2 * i], x0.x); vfma(a0, w2[2 * i + 1], x0.y);
            vfma(a1, w2[2 * i], x1.x); vfma(a1, w2[2 * i + 1], x1.y);
            vfma(a2, w2[2 * i], x2.x); vfma(a2, w2[2 * i + 1], x2.y);
            vfma(a3, w2[2 * i], x3.x); vfma(a3, w2[2 * i + 1], x3.y);
        }
        int pb = (gg << 5) + jj;
        psum[((q << 2) + 0) * 128 + pb] = red2(a0);
        psum[((q << 2) + 1) * 128 + pb] = red2(a1);
        psum[((q << 2) + 2) * 128 + pb] = red2(a2);
        psum[((q << 2) + 3) * 128 + pb] = red2(a3);
        __syncthreads();

        if (tid < 128) {
            float ri = psum[ob * 128 + jj]      + psum[(4 + ob) * 128 + jj];
            float rf = psum[ob * 128 + 32 + jj] + psum[(4 + ob) * 128 + 32 + jj];
            float rg = psum[ob * 128 + 64 + jj] + psum[(4 + ob) * 128 + 64 + jj];
            float ro = psum[ob * 128 + 96 + jj] + psum[(4 + ob) * 128 + 96 + jj];
            float iv = sigm(gxi + ri);
            float fv = sigm(gxf + rf);
            float gv = tanhf(gxg + rg);
            float ov = sigm(gxo + ro);
            c = fv * c + iv * gv;
            float h = ov * tanhf(c);
            hout[(size_t)((s << 5) + obg) * 512 + (dir << 8) + (hs << 5) + jj] = h;
        }

        // group sync: distributed flags. Arrive: one release-store to own slot
        // (no atomic serialization). Wait: 8 threads poll the 8 group flags in
        // parallel (one L2 round per probe for the whole group, not per peer).
        __syncthreads();
        if (tid == 0) {
            __threadfence();
            asm volatile("st.release.gpu.global.u32 [%0], %1;"
                         :: "l"(myflag), "r"((unsigned)(t + 1)) : "memory");
        }
        if (tid < 8) {
            unsigned v;
            do {
                asm volatile("ld.acquire.gpu.global.u32 %0, [%1];"
                             : "=r"(v) : "l"(peerflag) : "memory");
            } while (v < (unsigned)(t + 1));
        }
        __syncthreads();
    }
}

// ---------------- feats = h1 @ w_out^T + b_out ----------------
__global__ __launch_bounds__(256)
void feats_kernel(const float* __restrict__ h,
                  const float* __restrict__ w_out,
                  const float* __restrict__ b_out,
                  float* __restrict__ feats) {
    __shared__ float ws[NTAG * 512];
    int tid = threadIdx.x;
    for (int i = tid; i < NTAG * 512; i += 256) ws[i] = w_out[i];
    __syncthreads();
    int warp = tid >> 5, lane = tid & 31;
    int m = blockIdx.x * 8 + warp;          // 0..16383
    float hreg[16];
#pragma unroll
    for (int i = 0; i < 16; ++i) hreg[i] = h[(size_t)m * 512 + i * 32 + lane];
#pragma unroll
    for (int tg = 0; tg < NTAG; ++tg) {
        float acc = 0.f;
#pragma unroll
        for (int i = 0; i < 16; ++i) acc += hreg[i] * ws[tg * 512 + i * 32 + lane];
#pragma unroll
        for (int off = 16; off; off >>= 1) acc += __shfl_down_sync(0xffffffffu, acc, off);
        if (lane == 0) feats[(size_t)m * NTAG + tg] = acc + b_out[tg];
    }
}

// ---------------- Viterbi (1 warp per batch) ----------------
__global__ __launch_bounds__(32)
void viterbi_kernel(const float* __restrict__ feats,
                    const float* __restrict__ trans,
                    float* __restrict__ out) {
    __shared__ unsigned char bps[S_LEN][16];
    int b = blockIdx.x, t = threadIdx.x;
    int tc = (t < NTAG) ? t : NTAG - 1;
    float tr[NTAG];
#pragma unroll
    for (int p = 0; p < NTAG; ++p) tr[p] = trans[tc * NTAG + p];
    float fv = (t == START_TAG) ? 0.f : NEGV;

    for (int s = 0; s < S_LEN; ++s) {
        float best = -3.4e38f; int bp = 0;
#pragma unroll
        for (int p = 0; p < NTAG; ++p) {
            float fp = __shfl_sync(0xffffffffu, fv, p);
            float v = fp + tr[p];
            if (v > best) { best = v; bp = p; }
        }
        float feat = (t < NTAG) ? feats[(size_t)((s << 5) + b) * NTAG + t] : 0.f;
        fv = best + feat;
        if (t < NTAG) bps[s][t] = (unsigned char)bp;
    }

    float term = (t < NTAG) ? fv + trans[STOP_TAG * NTAG + t] : -3.4e38f;
    int idx = t;
#pragma unroll
    for (int off = 16; off; off >>= 1) {
        float ov = __shfl_down_sync(0xffffffffu, term, off);
        int oi = __shfl_down_sync(0xffffffffu, idx, off);
        if (ov > term || (ov == term && oi < idx)) { term = ov; idx = oi; }
    }
    if (t == 0) {
        out[b] = term;
        int tag = idx;
        for (int s = S_LEN - 1; s >= 0; --s) {
            out[32 + b * S_LEN + s] = (float)tag;
            tag = bps[s][tag];
        }
    }
}

// ---------------- launcher ----------------
extern "C" void kernel_launch(void* const* d_in, const int* in_sizes, int n_in,
                              void* d_out, int out_size) {
    const int*   x      = (const int*)d_in[0];
    const float* emb    = (const float*)d_in[2];
    const float* wih0f  = (const float*)d_in[3];
    const float* whh0f  = (const float*)d_in[4];
    const float* b0f    = (const float*)d_in[5];
    const float* wih0b  = (const float*)d_in[6];
    const float* whh0b  = (const float*)d_in[7];
    const float* b0b    = (const float*)d_in[8];
    const float* wih1f  = (const float*)d_in[9];
    const float* whh1f  = (const float*)d_in[10];
    const float* b1f    = (const float*)d_in[11];
    const float* wih1b  = (const float*)d_in[12];
    const float* whh1b  = (const float*)d_in[13];
    const float* b1b    = (const float*)d_in[14];
    const float* w_out  = (const float*)d_in[15];
    const float* b_out  = (const float*)d_in[16];
    const float* trans  = (const float*)d_in[17];
    float* out = (float*)d_out;

    float* xe = nullptr; float* gates = nullptr; float* h0 = nullptr;
    float* h1 = nullptr; float* feats = nullptr; unsigned* flg = nullptr;
    cudaGetSymbolAddress((void**)&xe, g_xe);
    cudaGetSymbolAddress((void**)&gates, g_gates);
    cudaGetSymbolAddress((void**)&h0, g_h0);
    cudaGetSymbolAddress((void**)&h1, g_h1);
    cudaGetSymbolAddress((void**)&feats, g_feats);
    cudaGetSymbolAddress((void**)&flg, g_flag);

    const size_t dirStride = (size_t)S_LEN * BATCH * 1024;

    embed_kernel<<<4096, 256>>>(x, emb, xe);

    sgemm_bias<<<dim3(16, 128), 256>>>(xe, wih0f, b0f, gates, HID);
    sgemm_bias<<<dim3(16, 128), 256>>>(xe, wih0b, b0b, gates + dirStride, HID);
    cudaMemsetAsync(flg, 0, 16 * 8 * 32 * sizeof(unsigned));
    lstm_layer<<<NCTA_LSTM, 256>>>(gates, whh0f, whh0b, h0);

    sgemm_bias<<<dim3(16, 128), 256>>>(h0, wih1f, b1f, gates, 2 * HID);
    sgemm_bias<<<dim3(16, 128), 256>>>(h0, wih1b, b1b, gates + dirStride, 2 * HID);
    cudaMemsetAsync(flg, 0, 16 * 8 * 32 * sizeof(unsigned));
    lstm_layer<<<NCTA_LSTM, 256>>>(gates, whh1f, whh1b, h1);

    feats_kernel<<<2048, 256>>>(h1, w_out, b_out, feats);
    viterbi_kernel<<<BATCH, 32>>>(feats, trans, out);
}